// round 5
// baseline (speedup 1.0000x reference)
#include <cuda_runtime.h>
#include <cuda_bf16.h>
#include <math.h>
#include <stdint.h>

// Problem constants
#define BATCH 8
#define SEQ   1024
#define CDIM  2048
#define NHEAD 16
#define NKV   4
#define HD    128
#define MROWS (BATCH*SEQ)          // 8192
#define KVDIM (NKV*HD)             // 512

// ---------------------------------------------------------------------------
// Scratch (__device__ globals; no allocation allowed)
// ---------------------------------------------------------------------------
__device__ __align__(16) float g_q[(size_t)MROWS * CDIM];    // 64 MB
__device__ __align__(16) float g_k[(size_t)MROWS * KVDIM];   // 16 MB
__device__ __align__(16) float g_v[(size_t)MROWS * KVDIM];   // 16 MB

// bf16 hi/lo split buffers
__device__ __align__(16) __nv_bfloat16 g_xh[(size_t)MROWS * CDIM];   // 32 MB
__device__ __align__(16) __nv_bfloat16 g_xl[(size_t)MROWS * CDIM];
__device__ __align__(16) __nv_bfloat16 g_yh[(size_t)MROWS * CDIM];
__device__ __align__(16) __nv_bfloat16 g_yl[(size_t)MROWS * CDIM];
// transposed + split weights: [N][K] layout (k-contiguous)
__device__ __align__(16) __nv_bfloat16 g_wqh[(size_t)CDIM * CDIM];
__device__ __align__(16) __nv_bfloat16 g_wql[(size_t)CDIM * CDIM];
__device__ __align__(16) __nv_bfloat16 g_wkh[(size_t)KVDIM * CDIM];
__device__ __align__(16) __nv_bfloat16 g_wkl[(size_t)KVDIM * CDIM];
__device__ __align__(16) __nv_bfloat16 g_wvh[(size_t)KVDIM * CDIM];
__device__ __align__(16) __nv_bfloat16 g_wvl[(size_t)KVDIM * CDIM];
__device__ __align__(16) __nv_bfloat16 g_woh[(size_t)CDIM * CDIM];
__device__ __align__(16) __nv_bfloat16 g_wol[(size_t)CDIM * CDIM];

// ---------------------------------------------------------------------------
// Split fp32 -> (hi, lo) bf16 pair, elementwise, same layout. n4 = n/4.
// ---------------------------------------------------------------------------
__global__ void split_f32(const float* __restrict__ in,
                          __nv_bfloat16* __restrict__ hi,
                          __nv_bfloat16* __restrict__ lo, int n4)
{
    int i = blockIdx.x * blockDim.x + threadIdx.x;
    if (i >= n4) return;
    float4 v = ((const float4*)in)[i];
    __nv_bfloat16 h0 = __float2bfloat16(v.x);
    __nv_bfloat16 h1 = __float2bfloat16(v.y);
    __nv_bfloat16 h2 = __float2bfloat16(v.z);
    __nv_bfloat16 h3 = __float2bfloat16(v.w);
    __nv_bfloat16 l0 = __float2bfloat16(v.x - __bfloat162float(h0));
    __nv_bfloat16 l1 = __float2bfloat16(v.y - __bfloat162float(h1));
    __nv_bfloat16 l2 = __float2bfloat16(v.z - __bfloat162float(h2));
    __nv_bfloat16 l3 = __float2bfloat16(v.w - __bfloat162float(h3));
    __nv_bfloat162 hh0; hh0.x = h0; hh0.y = h1;
    __nv_bfloat162 hh1; hh1.x = h2; hh1.y = h3;
    __nv_bfloat162 ll0; ll0.x = l0; ll0.y = l1;
    __nv_bfloat162 ll1; ll1.x = l2; ll1.y = l3;
    ((__nv_bfloat162*)hi)[2 * i]     = hh0;
    ((__nv_bfloat162*)hi)[2 * i + 1] = hh1;
    ((__nv_bfloat162*)lo)[2 * i]     = ll0;
    ((__nv_bfloat162*)lo)[2 * i + 1] = ll1;
}

// ---------------------------------------------------------------------------
// Transpose + split: w [K][N] fp32  ->  th, tl [N][K] bf16.
// Block (32,8), 32x32 tile via smem. K, N multiples of 32.
// ---------------------------------------------------------------------------
__global__ void transpose_split(const float* __restrict__ w,
                                __nv_bfloat16* __restrict__ th,
                                __nv_bfloat16* __restrict__ tl, int K, int N)
{
    __shared__ float tile[32][33];
    int x  = blockIdx.x * 32 + threadIdx.x;   // N index
    int y0 = blockIdx.y * 32;                 // K base
#pragma unroll
    for (int r = threadIdx.y; r < 32; r += 8)
        tile[r][threadIdx.x] = w[(size_t)(y0 + r) * N + x];
    __syncthreads();
    int n0 = blockIdx.x * 32;
    int kk = y0 + threadIdx.x;
#pragma unroll
    for (int r = threadIdx.y; r < 32; r += 8) {
        float v = tile[threadIdx.x][r];
        __nv_bfloat16 h = __float2bfloat16(v);
        th[(size_t)(n0 + r) * K + kk] = h;
        tl[(size_t)(n0 + r) * K + kk] = __float2bfloat16(v - __bfloat162float(h));
    }
}

// ---------------------------------------------------------------------------
// Split-bf16 tensor-core GEMM:
//   C[M][N] (fp32) = A[M][K] @ B[N][K]^T, computed as Ah*Bh + Al*Bh + Ah*Bl.
// Block: 128x128 tile, BK=32, 512 threads (16 warps as 4x4), warp tile 32x32.
// mma.sync.m16n8k16 row.col bf16->f32.
// Smem tiles padded to 40 bf16/row (20 words) -> conflict-free frag loads.
// ---------------------------------------------------------------------------
#define BM  128
#define BN  128
#define BKT 32
#define SPAD 40

__device__ __forceinline__ uint32_t lds32(const __nv_bfloat16* s, int off_half) {
    return *(const uint32_t*)(s + off_half);
}

__device__ __forceinline__ void mma_bf16(float c[4], const uint32_t a[4],
                                         const uint32_t b[2]) {
    asm volatile(
        "mma.sync.aligned.m16n8k16.row.col.f32.bf16.bf16.f32 "
        "{%0,%1,%2,%3}, {%4,%5,%6,%7}, {%8,%9}, {%0,%1,%2,%3};\n"
        : "+f"(c[0]), "+f"(c[1]), "+f"(c[2]), "+f"(c[3])
        : "r"(a[0]), "r"(a[1]), "r"(a[2]), "r"(a[3]), "r"(b[0]), "r"(b[1]));
}

__global__ __launch_bounds__(512, 1) void gemm_bf16split(
    const __nv_bfloat16* __restrict__ Ah, const __nv_bfloat16* __restrict__ Al,
    const __nv_bfloat16* __restrict__ Bh, const __nv_bfloat16* __restrict__ Bl,
    float* __restrict__ C, int M, int N, int K)
{
    __shared__ __nv_bfloat16 sAh[BM * SPAD];
    __shared__ __nv_bfloat16 sAl[BM * SPAD];
    __shared__ __nv_bfloat16 sBh[BN * SPAD];
    __shared__ __nv_bfloat16 sBl[BN * SPAD];   // 4 * 10240 B = 40 KB

    const int tid  = threadIdx.x;
    const int warp = tid >> 5;
    const int lane = tid & 31;
    const int g = lane >> 2;      // 0..7
    const int t = lane & 3;       // 0..3
    const int wm = (warp >> 2) * 32;   // warp row base within block tile
    const int wn = (warp & 3) * 32;    // warp col base

    const int lrow = tid >> 2;          // 0..127 (tile row for gmem loads)
    const int lcol = (tid & 3) * 8;     // 0,8,16,24 (bf16 offset)

    const size_t aoff = (size_t)(blockIdx.y * BM + lrow) * K + lcol;
    const size_t boff = (size_t)(blockIdx.x * BN + lrow) * K + lcol;
    const int srow = lrow * SPAD + lcol;

    float acc[2][4][4];
#pragma unroll
    for (int mi = 0; mi < 2; mi++)
#pragma unroll
        for (int nj = 0; nj < 4; nj++)
#pragma unroll
            for (int c = 0; c < 4; c++) acc[mi][nj][c] = 0.f;

    // preload tile 0
    {
        uint4 a_h = *(const uint4*)(Ah + aoff);
        uint4 a_l = *(const uint4*)(Al + aoff);
        uint4 b_h = *(const uint4*)(Bh + boff);
        uint4 b_l = *(const uint4*)(Bl + boff);
        *(uint4*)(sAh + srow) = a_h;
        *(uint4*)(sAl + srow) = a_l;
        *(uint4*)(sBh + srow) = b_h;
        *(uint4*)(sBl + srow) = b_l;
    }
    __syncthreads();

    const int ktiles = K / BKT;
    for (int kt = 0; kt < ktiles; kt++) {
        // prefetch next tile to registers
        uint4 pa_h, pa_l, pb_h, pb_l;
        if (kt + 1 < ktiles) {
            const int k0 = (kt + 1) * BKT;
            pa_h = *(const uint4*)(Ah + aoff + k0);
            pa_l = *(const uint4*)(Al + aoff + k0);
            pb_h = *(const uint4*)(Bh + boff + k0);
            pb_l = *(const uint4*)(Bl + boff + k0);
        }

        // compute current tile: two k16 chunks
#pragma unroll
        for (int kk = 0; kk < 2; kk++) {
            const int kbase = kk * 16 + 2 * t;
            uint32_t ah[2][4], al[2][4];
#pragma unroll
            for (int mi = 0; mi < 2; mi++) {
                const int r0 = wm + mi * 16 + g;
                ah[mi][0] = lds32(sAh, r0 * SPAD + kbase);
                ah[mi][1] = lds32(sAh, (r0 + 8) * SPAD + kbase);
                ah[mi][2] = lds32(sAh, r0 * SPAD + kbase + 8);
                ah[mi][3] = lds32(sAh, (r0 + 8) * SPAD + kbase + 8);
                al[mi][0] = lds32(sAl, r0 * SPAD + kbase);
                al[mi][1] = lds32(sAl, (r0 + 8) * SPAD + kbase);
                al[mi][2] = lds32(sAl, r0 * SPAD + kbase + 8);
                al[mi][3] = lds32(sAl, (r0 + 8) * SPAD + kbase + 8);
            }
            uint32_t bh[4][2], bl[4][2];
#pragma unroll
            for (int nj = 0; nj < 4; nj++) {
                const int rb = (wn + nj * 8 + g) * SPAD + kbase;
                bh[nj][0] = lds32(sBh, rb);
                bh[nj][1] = lds32(sBh, rb + 8);
                bl[nj][0] = lds32(sBl, rb);
                bl[nj][1] = lds32(sBl, rb + 8);
            }
#pragma unroll
            for (int mi = 0; mi < 2; mi++)
#pragma unroll
                for (int nj = 0; nj < 4; nj++) {
                    mma_bf16(acc[mi][nj], ah[mi], bh[nj]);
                    mma_bf16(acc[mi][nj], al[mi], bh[nj]);
                    mma_bf16(acc[mi][nj], ah[mi], bl[nj]);
                }
        }
        __syncthreads();
        if (kt + 1 < ktiles) {
            *(uint4*)(sAh + srow) = pa_h;
            *(uint4*)(sAl + srow) = pa_l;
            *(uint4*)(sBh + srow) = pb_h;
            *(uint4*)(sBl + srow) = pb_l;
        }
        __syncthreads();
    }

    // epilogue
#pragma unroll
    for (int mi = 0; mi < 2; mi++) {
        const int row = blockIdx.y * BM + wm + mi * 16 + g;
#pragma unroll
        for (int nj = 0; nj < 4; nj++) {
            const int col = blockIdx.x * BN + wn + nj * 8 + 2 * t;
            float2 v01 = make_float2(acc[mi][nj][0], acc[mi][nj][1]);
            float2 v23 = make_float2(acc[mi][nj][2], acc[mi][nj][3]);
            *(float2*)(C + (size_t)row * N + col)       = v01;
            *(float2*)(C + (size_t)(row + 8) * N + col) = v23;
        }
    }
}

// ---------------------------------------------------------------------------
// RoPE (in place). buf: [MROWS, nheads*128]. t = row % SEQ. Full-head rotation.
// scale folds 1/sqrt(hd) into q.
// ---------------------------------------------------------------------------
__global__ void rope_kernel(float* __restrict__ buf,
                            const float* __restrict__ sinb,
                            const float* __restrict__ cosb,
                            int nheads, int rowwidth, float scale, int total)
{
    int idx = blockIdx.x * blockDim.x + threadIdx.x;
    if (idx >= total) return;
    int d = idx & 63;
    int tmp = idx >> 6;
    int h = tmp % nheads;
    int row = tmp / nheads;
    int t = row & (SEQ - 1);
    float* p = buf + (size_t)row * rowwidth + h * HD;
    float a = p[d], b = p[d + 64];
    float c0 = cosb[t * HD + d],      s0 = sinb[t * HD + d];
    float c1 = cosb[t * HD + d + 64], s1 = sinb[t * HD + d + 64];
    p[d]      = (a * c0 - b * s0) * scale;
    p[d + 64] = (b * c1 + a * s1) * scale;
}

// ---------------------------------------------------------------------------
// Flash attention, fp32, causal. Writes y directly as split hi/lo bf16
// (feeds the wo tensor-core GEMM without an intermediate fp32 y buffer).
// Grid: (T/64, NHEAD, BATCH). Block: 256 threads (8 warps).
// ---------------------------------------------------------------------------
__device__ __forceinline__ float dot4(float4 a, float4 b) {
    return a.x * b.x + a.y * b.y + a.z * b.z + a.w * b.w;
}
__device__ __forceinline__ void fma4(float4& o, float p, float4 v) {
    o.x += p * v.x; o.y += p * v.y; o.z += p * v.z; o.w += p * v.w;
}

__global__ __launch_bounds__(256) void attn_kernel(
    const float* __restrict__ q, const float* __restrict__ k,
    const float* __restrict__ v,
    __nv_bfloat16* __restrict__ yh, __nv_bfloat16* __restrict__ yl)
{
    __shared__ float4 kbuf[32][32];
    __shared__ float4 vbuf[32][32];

    const int qt = blockIdx.x;
    const int h  = blockIdx.y;
    const int b  = blockIdx.z;
    const int kvh = h & (NKV - 1);

    const int tid  = threadIdx.x;
    const int lane = tid & 31;
    const int warp = tid >> 5;
    const int g    = lane & 3;
    const int rowi = warp * 8 + (lane >> 2);
    const int trow = qt * 64 + rowi;

    int rot2[4];
#pragma unroll
    for (int s = 0; s < 4; s++) rot2[s] = ((s + g) & 3) * 2;

    const float* qbase = q + (size_t)(b * SEQ + trow) * CDIM + h * HD + g * 32;
    float4 qreg[8];
#pragma unroll
    for (int s = 0; s < 4; s++) {
        qreg[s * 2]     = *(const float4*)(qbase + rot2[s] * 4);
        qreg[s * 2 + 1] = *(const float4*)(qbase + rot2[s] * 4 + 4);
    }

    float4 o[8];
#pragma unroll
    for (int i = 0; i < 8; i++) o[i] = make_float4(0.f, 0.f, 0.f, 0.f);
    float mval = -INFINITY, l = 0.f;

    const int ntiles = 2 * qt + 2;
    const int lr = tid >> 3;
    const int lc = tid & 7;
    const float* kbase = k + (size_t)(b * SEQ) * KVDIM + kvh * HD;
    const float* vbase = v + (size_t)(b * SEQ) * KVDIM + kvh * HD;

    for (int kt = 0; kt < ntiles; kt++) {
        {
            const float* kp = kbase + (size_t)(kt * 32 + lr) * KVDIM;
            const float* vp = vbase + (size_t)(kt * 32 + lr) * KVDIM;
#pragma unroll
            for (int it = 0; it < 4; it++)
                kbuf[lr][lc + it * 8] = *(const float4*)(kp + (lc + it * 8) * 4);
#pragma unroll
            for (int it = 0; it < 4; it++)
                vbuf[lr][lc + it * 8] = *(const float4*)(vp + (lc + it * 8) * 4);
        }
        __syncthreads();

        float sreg[32];
#pragma unroll
        for (int j = 0; j < 32; j++) {
            const float4* kr = &kbuf[j][g * 8];
            float acc = 0.f;
#pragma unroll
            for (int s = 0; s < 4; s++) {
                acc += dot4(qreg[s * 2],     kr[rot2[s]]);
                acc += dot4(qreg[s * 2 + 1], kr[rot2[s] + 1]);
            }
            acc += __shfl_xor_sync(0xffffffffu, acc, 1);
            acc += __shfl_xor_sync(0xffffffffu, acc, 2);
            sreg[j] = acc;
        }

        const int kt32 = kt * 32;
        float mnew = mval;
#pragma unroll
        for (int j = 0; j < 32; j++) {
            if (kt32 + j > trow) sreg[j] = -INFINITY;
            mnew = fmaxf(mnew, sreg[j]);
        }
        float alpha = __expf(mval - mnew);
        mval = mnew;

        float preg[8];
        float psum = 0.f;
#pragma unroll
        for (int jj = 0; jj < 8; jj++) {
            float pv = __expf(sreg[jj * 4 + g] - mnew);
            preg[jj] = pv;
            psum += pv;
        }
        psum += __shfl_xor_sync(0xffffffffu, psum, 1);
        psum += __shfl_xor_sync(0xffffffffu, psum, 2);
        l = l * alpha + psum;
#pragma unroll
        for (int i = 0; i < 8; i++) {
            o[i].x *= alpha; o[i].y *= alpha; o[i].z *= alpha; o[i].w *= alpha;
        }

#pragma unroll
        for (int j = 0; j < 32; j++) {
            float pj = __shfl_sync(0xffffffffu, preg[j >> 2], (lane & ~3) | (j & 3));
            const float4* vr = &vbuf[j][g * 8];
#pragma unroll
            for (int s = 0; s < 4; s++) {
                fma4(o[s * 2],     pj, vr[rot2[s]]);
                fma4(o[s * 2 + 1], pj, vr[rot2[s] + 1]);
            }
        }
        __syncthreads();
    }

    // ---- normalize + split to hi/lo bf16 + store (rotated order) ----
    const float inv = 1.0f / l;
    const size_t ybeli = (size_t)(b * SEQ + trow) * CDIM + h * HD + g * 32;
    __nv_bfloat16* yhb = yh + ybeli;
    __nv_bfloat16* ylb = yl + ybeli;
#pragma unroll
    for (int s = 0; s < 4; s++) {
        float vals[8];
        *(float4*)&vals[0] = o[s * 2];
        *(float4*)&vals[4] = o[s * 2 + 1];
        __nv_bfloat16 hi8[8], lo8[8];
#pragma unroll
        for (int e = 0; e < 8; e++) {
            float f = vals[e] * inv;
            __nv_bfloat16 hh = __float2bfloat16(f);
            hi8[e] = hh;
            lo8[e] = __float2bfloat16(f - __bfloat162float(hh));
        }
        *(uint4*)(yhb + rot2[s] * 4) = *(const uint4*)hi8;
        *(uint4*)(ylb + rot2[s] * 4) = *(const uint4*)lo8;
    }
}

// ---------------------------------------------------------------------------
extern "C" void kernel_launch(void* const* d_in, const int* in_sizes, int n_in,
                              void* d_out, int out_size)
{
    const float* x    = (const float*)d_in[0];
    const float* wq   = (const float*)d_in[1];
    const float* wk   = (const float*)d_in[2];
    const float* wv   = (const float*)d_in[3];
    const float* wo   = (const float*)d_in[4];
    const float* sinb = (const float*)d_in[5];
    const float* cosb = (const float*)d_in[6];
    float* out = (float*)d_out;

    float *q, *k, *v;
    __nv_bfloat16 *xh, *xl, *yh, *yl;
    __nv_bfloat16 *wqh, *wql, *wkh, *wkl, *wvh, *wvl, *woh, *wol;
    cudaGetSymbolAddress((void**)&q, g_q);
    cudaGetSymbolAddress((void**)&k, g_k);
    cudaGetSymbolAddress((void**)&v, g_v);
    cudaGetSymbolAddress((void**)&xh, g_xh);
    cudaGetSymbolAddress((void**)&xl, g_xl);
    cudaGetSymbolAddress((void**)&yh, g_yh);
    cudaGetSymbolAddress((void**)&yl, g_yl);
    cudaGetSymbolAddress((void**)&wqh, g_wqh);
    cudaGetSymbolAddress((void**)&wql, g_wql);
    cudaGetSymbolAddress((void**)&wkh, g_wkh);
    cudaGetSymbolAddress((void**)&wkl, g_wkl);
    cudaGetSymbolAddress((void**)&wvh, g_wvh);
    cudaGetSymbolAddress((void**)&wvl, g_wvl);
    cudaGetSymbolAddress((void**)&woh, g_woh);
    cudaGetSymbolAddress((void**)&wol, g_wol);

    // ---- split x, transpose+split weights ----
    {
        int n4 = MROWS * CDIM / 4;
        split_f32<<<(n4 + 255) / 256, 256>>>(x, xh, xl, n4);
    }
    dim3 tb(32, 8);
    transpose_split<<<dim3(CDIM / 32, CDIM / 32), tb>>>(wq, wqh, wql, CDIM, CDIM);
    transpose_split<<<dim3(KVDIM / 32, CDIM / 32), tb>>>(wk, wkh, wkl, CDIM, KVDIM);
    transpose_split<<<dim3(KVDIM / 32, CDIM / 32), tb>>>(wv, wvh, wvl, CDIM, KVDIM);
    transpose_split<<<dim3(CDIM / 32, CDIM / 32), tb>>>(wo, woh, wol, CDIM, CDIM);

    // ---- QKV projections (tensor-core split-bf16) ----
    gemm_bf16split<<<dim3(CDIM / BN, MROWS / BM), 512>>>(xh, xl, wqh, wql, q,
                                                         MROWS, CDIM, CDIM);
    gemm_bf16split<<<dim3(KVDIM / BN, MROWS / BM), 512>>>(xh, xl, wkh, wkl, k,
                                                          MROWS, KVDIM, CDIM);
    gemm_bf16split<<<dim3(KVDIM / BN, MROWS / BM), 512>>>(xh, xl, wvh, wvl, v,
                                                          MROWS, KVDIM, CDIM);

    // ---- RoPE (q also gets 1/sqrt(hd)) ----
    const float scale = 0.08838834764831845f;  // 1/sqrt(128)
    int nq = MROWS * NHEAD * 64;
    int nk = MROWS * NKV * 64;
    rope_kernel<<<(nq + 255) / 256, 256>>>(q, sinb, cosb, NHEAD, CDIM, scale, nq);
    rope_kernel<<<(nk + 255) / 256, 256>>>(k, sinb, cosb, NKV, KVDIM, 1.0f, nk);

    // ---- Attention (writes split bf16 y directly) ----
    attn_kernel<<<dim3(SEQ / 64, NHEAD, BATCH), 256>>>(q, k, v, yh, yl);

    // ---- Output projection ----
    gemm_bf16split<<<dim3(CDIM / BN, MROWS / BM), 512>>>(yh, yl, woh, wol, out,
                                                         MROWS, CDIM, CDIM);
}

// round 7
// speedup vs baseline: 1.5429x; 1.5429x over previous
#include <cuda_runtime.h>
#include <cuda_bf16.h>
#include <math.h>
#include <stdint.h>

// Problem constants
#define BATCH 8
#define SEQ   1024
#define CDIM  2048
#define NHEAD 16
#define NKV   4
#define HD    128
#define MROWS (BATCH*SEQ)          // 8192
#define KVDIM (NKV*HD)             // 512

// ---------------------------------------------------------------------------
// Scratch (__device__ globals; no allocation allowed)
// ---------------------------------------------------------------------------
__device__ __align__(16) float g_q[(size_t)MROWS * CDIM];    // 64 MB
__device__ __align__(16) float g_k[(size_t)MROWS * KVDIM];   // 16 MB
__device__ __align__(16) float g_v[(size_t)MROWS * KVDIM];   // 16 MB

// bf16 hi/lo split buffers
__device__ __align__(16) __nv_bfloat16 g_xh[(size_t)MROWS * CDIM];
__device__ __align__(16) __nv_bfloat16 g_xl[(size_t)MROWS * CDIM];
__device__ __align__(16) __nv_bfloat16 g_yh[(size_t)MROWS * CDIM];
__device__ __align__(16) __nv_bfloat16 g_yl[(size_t)MROWS * CDIM];
__device__ __align__(16) __nv_bfloat16 g_kh[(size_t)MROWS * KVDIM];
__device__ __align__(16) __nv_bfloat16 g_kl[(size_t)MROWS * KVDIM];
__device__ __align__(16) __nv_bfloat16 g_vh[(size_t)MROWS * KVDIM];
__device__ __align__(16) __nv_bfloat16 g_vl[(size_t)MROWS * KVDIM];
// transposed + split weights: [N][K] layout (k-contiguous)
__device__ __align__(16) __nv_bfloat16 g_wqh[(size_t)CDIM * CDIM];
__device__ __align__(16) __nv_bfloat16 g_wql[(size_t)CDIM * CDIM];
__device__ __align__(16) __nv_bfloat16 g_wkh[(size_t)KVDIM * CDIM];
__device__ __align__(16) __nv_bfloat16 g_wkl[(size_t)KVDIM * CDIM];
__device__ __align__(16) __nv_bfloat16 g_wvh[(size_t)KVDIM * CDIM];
__device__ __align__(16) __nv_bfloat16 g_wvl[(size_t)KVDIM * CDIM];
__device__ __align__(16) __nv_bfloat16 g_woh[(size_t)CDIM * CDIM];
__device__ __align__(16) __nv_bfloat16 g_wol[(size_t)CDIM * CDIM];

// ---------------------------------------------------------------------------
__device__ __forceinline__ void split2(float x, float y, uint32_t& hi, uint32_t& lo) {
    __nv_bfloat16 hx = __float2bfloat16(x), hy = __float2bfloat16(y);
    __nv_bfloat162 hp; hp.x = hx; hp.y = hy;
    __nv_bfloat162 lp;
    lp.x = __float2bfloat16(x - __bfloat162float(hx));
    lp.y = __float2bfloat16(y - __bfloat162float(hy));
    hi = *(uint32_t*)&hp;
    lo = *(uint32_t*)&lp;
}

// ---------------------------------------------------------------------------
// Split fp32 -> (hi, lo) bf16 pair, elementwise, same layout. n4 = n/4.
// ---------------------------------------------------------------------------
__global__ void split_f32(const float* __restrict__ in,
                          __nv_bfloat16* __restrict__ hi,
                          __nv_bfloat16* __restrict__ lo, int n4)
{
    int i = blockIdx.x * blockDim.x + threadIdx.x;
    if (i >= n4) return;
    float4 v = ((const float4*)in)[i];
    uint32_t h0, l0, h1, l1;
    split2(v.x, v.y, h0, l0);
    split2(v.z, v.w, h1, l1);
    ((uint32_t*)hi)[2 * i]     = h0;
    ((uint32_t*)hi)[2 * i + 1] = h1;
    ((uint32_t*)lo)[2 * i]     = l0;
    ((uint32_t*)lo)[2 * i + 1] = l1;
}

// ---------------------------------------------------------------------------
// Transpose + split: w [K][N] fp32  ->  th, tl [N][K] bf16.
// ---------------------------------------------------------------------------
__global__ void transpose_split(const float* __restrict__ w,
                                __nv_bfloat16* __restrict__ th,
                                __nv_bfloat16* __restrict__ tl, int K, int N)
{
    __shared__ float tile[32][33];
    int x  = blockIdx.x * 32 + threadIdx.x;
    int y0 = blockIdx.y * 32;
#pragma unroll
    for (int r = threadIdx.y; r < 32; r += 8)
        tile[r][threadIdx.x] = w[(size_t)(y0 + r) * N + x];
    __syncthreads();
    int n0 = blockIdx.x * 32;
    int kk = y0 + threadIdx.x;
#pragma unroll
    for (int r = threadIdx.y; r < 32; r += 8) {
        float v = tile[threadIdx.x][r];
        __nv_bfloat16 h = __float2bfloat16(v);
        th[(size_t)(n0 + r) * K + kk] = h;
        tl[(size_t)(n0 + r) * K + kk] = __float2bfloat16(v - __bfloat162float(h));
    }
}

// ---------------------------------------------------------------------------
// mma.sync m16n8k16 bf16 -> f32 (hardware-validated fragment layouts)
// ---------------------------------------------------------------------------
__device__ __forceinline__ void mma_bf16(float c[4], const uint32_t a[4],
                                         const uint32_t b[2]) {
    asm volatile(
        "mma.sync.aligned.m16n8k16.row.col.f32.bf16.bf16.f32 "
        "{%0,%1,%2,%3}, {%4,%5,%6,%7}, {%8,%9}, {%0,%1,%2,%3};\n"
        : "+f"(c[0]), "+f"(c[1]), "+f"(c[2]), "+f"(c[3])
        : "r"(a[0]), "r"(a[1]), "r"(a[2]), "r"(a[3]), "r"(b[0]), "r"(b[1]));
}

// ---------------------------------------------------------------------------
// Split-bf16 tensor-core GEMM (validated at 4163us baseline).
// ---------------------------------------------------------------------------
#define BM  128
#define BN  128
#define BKT 32
#define SPAD 40

__device__ __forceinline__ uint32_t lds32(const __nv_bfloat16* s, int off_half) {
    return *(const uint32_t*)(s + off_half);
}

__global__ __launch_bounds__(512, 1) void gemm_bf16split(
    const __nv_bfloat16* __restrict__ Ah, const __nv_bfloat16* __restrict__ Al,
    const __nv_bfloat16* __restrict__ Bh, const __nv_bfloat16* __restrict__ Bl,
    float* __restrict__ C, int M, int N, int K)
{
    __shared__ __nv_bfloat16 sAh[BM * SPAD];
    __shared__ __nv_bfloat16 sAl[BM * SPAD];
    __shared__ __nv_bfloat16 sBh[BN * SPAD];
    __shared__ __nv_bfloat16 sBl[BN * SPAD];

    const int tid  = threadIdx.x;
    const int warp = tid >> 5;
    const int lane = tid & 31;
    const int g = lane >> 2;
    const int t = lane & 3;
    const int wm = (warp >> 2) * 32;
    const int wn = (warp & 3) * 32;

    const int lrow = tid >> 2;
    const int lcol = (tid & 3) * 8;

    const size_t aoff = (size_t)(blockIdx.y * BM + lrow) * K + lcol;
    const size_t boff = (size_t)(blockIdx.x * BN + lrow) * K + lcol;
    const int srow = lrow * SPAD + lcol;

    float acc[2][4][4];
#pragma unroll
    for (int mi = 0; mi < 2; mi++)
#pragma unroll
        for (int nj = 0; nj < 4; nj++)
#pragma unroll
            for (int c = 0; c < 4; c++) acc[mi][nj][c] = 0.f;

    {
        uint4 a_h = *(const uint4*)(Ah + aoff);
        uint4 a_l = *(const uint4*)(Al + aoff);
        uint4 b_h = *(const uint4*)(Bh + boff);
        uint4 b_l = *(const uint4*)(Bl + boff);
        *(uint4*)(sAh + srow) = a_h;
        *(uint4*)(sAl + srow) = a_l;
        *(uint4*)(sBh + srow) = b_h;
        *(uint4*)(sBl + srow) = b_l;
    }
    __syncthreads();

    const int ktiles = K / BKT;
    for (int kt = 0; kt < ktiles; kt++) {
        uint4 pa_h, pa_l, pb_h, pb_l;
        if (kt + 1 < ktiles) {
            const int k0 = (kt + 1) * BKT;
            pa_h = *(const uint4*)(Ah + aoff + k0);
            pa_l = *(const uint4*)(Al + aoff + k0);
            pb_h = *(const uint4*)(Bh + boff + k0);
            pb_l = *(const uint4*)(Bl + boff + k0);
        }

#pragma unroll
        for (int kk = 0; kk < 2; kk++) {
            const int kbase = kk * 16 + 2 * t;
            uint32_t ah[2][4], al[2][4];
#pragma unroll
            for (int mi = 0; mi < 2; mi++) {
                const int r0 = wm + mi * 16 + g;
                ah[mi][0] = lds32(sAh, r0 * SPAD + kbase);
                ah[mi][1] = lds32(sAh, (r0 + 8) * SPAD + kbase);
                ah[mi][2] = lds32(sAh, r0 * SPAD + kbase + 8);
                ah[mi][3] = lds32(sAh, (r0 + 8) * SPAD + kbase + 8);
                al[mi][0] = lds32(sAl, r0 * SPAD + kbase);
                al[mi][1] = lds32(sAl, (r0 + 8) * SPAD + kbase);
                al[mi][2] = lds32(sAl, r0 * SPAD + kbase + 8);
                al[mi][3] = lds32(sAl, (r0 + 8) * SPAD + kbase + 8);
            }
            uint32_t bh[4][2], bl[4][2];
#pragma unroll
            for (int nj = 0; nj < 4; nj++) {
                const int rb = (wn + nj * 8 + g) * SPAD + kbase;
                bh[nj][0] = lds32(sBh, rb);
                bh[nj][1] = lds32(sBh, rb + 8);
                bl[nj][0] = lds32(sBl, rb);
                bl[nj][1] = lds32(sBl, rb + 8);
            }
#pragma unroll
            for (int mi = 0; mi < 2; mi++)
#pragma unroll
                for (int nj = 0; nj < 4; nj++) {
                    mma_bf16(acc[mi][nj], ah[mi], bh[nj]);
                    mma_bf16(acc[mi][nj], al[mi], bh[nj]);
                    mma_bf16(acc[mi][nj], ah[mi], bl[nj]);
                }
        }
        __syncthreads();
        if (kt + 1 < ktiles) {
            *(uint4*)(sAh + srow) = pa_h;
            *(uint4*)(sAl + srow) = pa_l;
            *(uint4*)(sBh + srow) = pb_h;
            *(uint4*)(sBl + srow) = pb_l;
        }
        __syncthreads();
    }

#pragma unroll
    for (int mi = 0; mi < 2; mi++) {
        const int row = blockIdx.y * BM + wm + mi * 16 + g;
#pragma unroll
        for (int nj = 0; nj < 4; nj++) {
            const int col = blockIdx.x * BN + wn + nj * 8 + 2 * t;
            float2 v01 = make_float2(acc[mi][nj][0], acc[mi][nj][1]);
            float2 v23 = make_float2(acc[mi][nj][2], acc[mi][nj][3]);
            *(float2*)(C + (size_t)row * N + col)       = v01;
            *(float2*)(C + (size_t)(row + 8) * N + col) = v23;
        }
    }
}

// ---------------------------------------------------------------------------
// RoPE (in place), scale folds 1/sqrt(hd) into q.
// ---------------------------------------------------------------------------
__global__ void rope_kernel(float* __restrict__ buf,
                            const float* __restrict__ sinb,
                            const float* __restrict__ cosb,
                            int nheads, int rowwidth, float scale, int total)
{
    int idx = blockIdx.x * blockDim.x + threadIdx.x;
    if (idx >= total) return;
    int d = idx & 63;
    int tmp = idx >> 6;
    int h = tmp % nheads;
    int row = tmp / nheads;
    int t = row & (SEQ - 1);
    float* p = buf + (size_t)row * rowwidth + h * HD;
    float a = p[d], b = p[d + 64];
    float c0 = cosb[t * HD + d],      s0 = sinb[t * HD + d];
    float c1 = cosb[t * HD + d + 64], s1 = sinb[t * HD + d + 64];
    p[d]      = (a * c0 - b * s0) * scale;
    p[d + 64] = (b * c1 + a * s1) * scale;
}

// ---------------------------------------------------------------------------
// Tensor-core flash attention, causal, split-bf16 (3-pass) QK^T and PV.
// Block: 128 threads (4 warps), 64 q rows per block, key tiles of 64.
// Grid: (SEQ/64, NHEAD, BATCH).
// smem (dynamic, 71680 B):
//   sKh/sKl: K tile [64][136] bf16   (B operand for QK^T; word stride 68==4
//            mod 32 -> bank = 4g+t, conflict-free)
//   sVh/sVl: V^T tile [128][72] bf16 (B operand for PV; word stride 36==4
//            mod 32 -> conflict-free; 66 would alias to bank g+t = 4-way)
//   sQ (aliases K region before main loop): [64][132] fp32 staging
// ---------------------------------------------------------------------------
#define KPADA 136
#define VPAD  72
#define ATT_SMEM_BYTES ((8704 * 2 + 9216 * 2) * 2)   // 71680

__global__ __launch_bounds__(128) void attn_tc(
    const float* __restrict__ q,
    const __nv_bfloat16* __restrict__ kh, const __nv_bfloat16* __restrict__ kl,
    const __nv_bfloat16* __restrict__ vh, const __nv_bfloat16* __restrict__ vl,
    __nv_bfloat16* __restrict__ yh, __nv_bfloat16* __restrict__ yl)
{
    extern __shared__ __nv_bfloat16 sm[];
    __nv_bfloat16* sKh = sm;            // 8704 halves
    __nv_bfloat16* sKl = sm + 8704;
    __nv_bfloat16* sVh = sm + 17408;    // 9216 halves
    __nv_bfloat16* sVl = sm + 26624;
    float* sQ = (float*)sm;             // [64][132] fp32, pre-loop only

    const int qt = blockIdx.x, h = blockIdx.y, b = blockIdx.z;
    const int kvh = h & (NKV - 1);
    const int tid = threadIdx.x, lane = tid & 31, warp = tid >> 5;
    const int g = lane >> 2, t = lane & 3;
    const int row0  = warp * 16 + g;        // local q row (and row0+8)
    const int trow0 = qt * 64 + row0;
    const int trow1 = trow0 + 8;

    // ---- stage Q tile (coalesced) ----
    {
        const float* qb = q + (size_t)(b * SEQ + qt * 64) * CDIM + h * HD;
        for (int i = tid; i < 64 * 32; i += 128) {
            int r = i >> 5, c = i & 31;
            *(float4*)&sQ[r * 132 + c * 4] = *(const float4*)(qb + (size_t)r * CDIM + c * 4);
        }
    }
    __syncthreads();

    // ---- extract Q A-fragments, hi/lo split ----
    uint32_t qhf[8][4], qlf[8][4];
#pragma unroll
    for (int kb = 0; kb < 8; kb++) {
        int k0 = kb * 16 + 2 * t;
        float2 f0 = *(float2*)&sQ[row0 * 132 + k0];
        float2 f1 = *(float2*)&sQ[(row0 + 8) * 132 + k0];
        float2 f2 = *(float2*)&sQ[row0 * 132 + k0 + 8];
        float2 f3 = *(float2*)&sQ[(row0 + 8) * 132 + k0 + 8];
        split2(f0.x, f0.y, qhf[kb][0], qlf[kb][0]);
        split2(f1.x, f1.y, qhf[kb][1], qlf[kb][1]);
        split2(f2.x, f2.y, qhf[kb][2], qlf[kb][2]);
        split2(f3.x, f3.y, qhf[kb][3], qlf[kb][3]);
    }
    __syncthreads();

    float O[16][4];
#pragma unroll
    for (int nb = 0; nb < 16; nb++)
#pragma unroll
        for (int c = 0; c < 4; c++) O[nb][c] = 0.f;
    float m0 = -INFINITY, m1 = -INFINITY, l0 = 0.f, l1 = 0.f;

    for (int kt = 0; kt <= qt; kt++) {
        // ---- load K tile (straight) and V tile (transposed) ----
        {
            const size_t kvrow = (size_t)(b * SEQ + kt * 64);
            for (int i = tid; i < 1024; i += 128) {
                int key = i >> 4, seg = i & 15;
                size_t src = (kvrow + key) * KVDIM + (size_t)kvh * HD + seg * 8;
                *(uint4*)&sKh[key * KPADA + seg * 8] = *(const uint4*)(kh + src);
                *(uint4*)&sKl[key * KPADA + seg * 8] = *(const uint4*)(kl + src);
                uint4 v4h = *(const uint4*)(vh + src);
                uint4 v4l = *(const uint4*)(vl + src);
                int d0 = seg * 8;
                const __nv_bfloat16* ph = (const __nv_bfloat16*)&v4h;
                const __nv_bfloat16* pl = (const __nv_bfloat16*)&v4l;
#pragma unroll
                for (int e = 0; e < 8; e++) {
                    sVh[(d0 + e) * VPAD + key] = ph[e];
                    sVl[(d0 + e) * VPAD + key] = pl[e];
                }
            }
        }
        __syncthreads();

        // ---- scores S = q . k^T (3-pass split) ----
        float S[8][4];
#pragma unroll
        for (int nb = 0; nb < 8; nb++)
#pragma unroll
            for (int c = 0; c < 4; c++) S[nb][c] = 0.f;

#pragma unroll
        for (int kb = 0; kb < 8; kb++) {
#pragma unroll
            for (int nb = 0; nb < 8; nb++) {
                const int ba = (nb * 8 + g) * KPADA + kb * 16 + 2 * t;
                uint32_t bh[2], bl[2];
                bh[0] = lds32(sKh, ba);
                bh[1] = lds32(sKh, ba + 8);
                bl[0] = lds32(sKl, ba);
                bl[1] = lds32(sKl, ba + 8);
                mma_bf16(S[nb], qhf[kb], bh);
                mma_bf16(S[nb], qlf[kb], bh);
                mma_bf16(S[nb], qhf[kb], bl);
            }
        }

        // ---- causal mask (diagonal tile only) ----
        if (kt == qt) {
#pragma unroll
            for (int nb = 0; nb < 8; nb++) {
                int kc = kt * 64 + nb * 8 + 2 * t;
                if (kc > trow0)     S[nb][0] = -INFINITY;
                if (kc + 1 > trow0) S[nb][1] = -INFINITY;
                if (kc > trow1)     S[nb][2] = -INFINITY;
                if (kc + 1 > trow1) S[nb][3] = -INFINITY;
            }
        }

        // ---- online softmax ----
        float mx0 = m0, mx1 = m1;
#pragma unroll
        for (int nb = 0; nb < 8; nb++) {
            mx0 = fmaxf(mx0, fmaxf(S[nb][0], S[nb][1]));
            mx1 = fmaxf(mx1, fmaxf(S[nb][2], S[nb][3]));
        }
        mx0 = fmaxf(mx0, __shfl_xor_sync(0xffffffffu, mx0, 1));
        mx0 = fmaxf(mx0, __shfl_xor_sync(0xffffffffu, mx0, 2));
        mx1 = fmaxf(mx1, __shfl_xor_sync(0xffffffffu, mx1, 1));
        mx1 = fmaxf(mx1, __shfl_xor_sync(0xffffffffu, mx1, 2));

        float al0 = __expf(m0 - mx0);
        float al1 = __expf(m1 - mx1);
        m0 = mx0; m1 = mx1;

        float ps0 = 0.f, ps1 = 0.f;
#pragma unroll
        for (int nb = 0; nb < 8; nb++) {
            S[nb][0] = __expf(S[nb][0] - m0);
            S[nb][1] = __expf(S[nb][1] - m0);
            S[nb][2] = __expf(S[nb][2] - m1);
            S[nb][3] = __expf(S[nb][3] - m1);
            ps0 += S[nb][0] + S[nb][1];
            ps1 += S[nb][2] + S[nb][3];
        }
        l0 = l0 * al0 + ps0;
        l1 = l1 * al1 + ps1;

#pragma unroll
        for (int nb = 0; nb < 16; nb++) {
            O[nb][0] *= al0; O[nb][1] *= al0;
            O[nb][2] *= al1; O[nb][3] *= al1;
        }

        // ---- PV: O += P @ V (3-pass split), P built from S fragments ----
#pragma unroll
        for (int kb = 0; kb < 4; kb++) {
            uint32_t aPh[4], aPl[4];
            split2(S[2 * kb][0],     S[2 * kb][1],     aPh[0], aPl[0]);
            split2(S[2 * kb][2],     S[2 * kb][3],     aPh[1], aPl[1]);
            split2(S[2 * kb + 1][0], S[2 * kb + 1][1], aPh[2], aPl[2]);
            split2(S[2 * kb + 1][2], S[2 * kb + 1][3], aPh[3], aPl[3]);
#pragma unroll
            for (int nb = 0; nb < 16; nb++) {
                const int ba = (nb * 8 + g) * VPAD + kb * 16 + 2 * t;
                uint32_t bh[2], bl[2];
                bh[0] = lds32(sVh, ba);
                bh[1] = lds32(sVh, ba + 8);
                bl[0] = lds32(sVl, ba);
                bl[1] = lds32(sVl, ba + 8);
                mma_bf16(O[nb], aPh, bh);
                mma_bf16(O[nb], aPl, bh);
                mma_bf16(O[nb], aPh, bl);
            }
        }
        __syncthreads();   // tiles consumed; safe to overwrite next iter
    }

    // ---- final normalize + split-bf16 store ----
    l0 += __shfl_xor_sync(0xffffffffu, l0, 1);
    l0 += __shfl_xor_sync(0xffffffffu, l0, 2);
    l1 += __shfl_xor_sync(0xffffffffu, l1, 1);
    l1 += __shfl_xor_sync(0xffffffffu, l1, 2);
    const float inv0 = 1.f / l0, inv1 = 1.f / l1;

    const size_t ybase0 = (size_t)(b * SEQ + trow0) * CDIM + h * HD;
    const size_t ybase1 = (size_t)(b * SEQ + trow1) * CDIM + h * HD;
#pragma unroll
    for (int nb = 0; nb < 16; nb++) {
        const int d = nb * 8 + 2 * t;
        uint32_t hi, lo;
        split2(O[nb][0] * inv0, O[nb][1] * inv0, hi, lo);
        *(uint32_t*)&yh[ybase0 + d] = hi;
        *(uint32_t*)&yl[ybase0 + d] = lo;
        split2(O[nb][2] * inv1, O[nb][3] * inv1, hi, lo);
        *(uint32_t*)&yh[ybase1 + d] = hi;
        *(uint32_t*)&yl[ybase1 + d] = lo;
    }
}

// ---------------------------------------------------------------------------
extern "C" void kernel_launch(void* const* d_in, const int* in_sizes, int n_in,
                              void* d_out, int out_size)
{
    const float* x    = (const float*)d_in[0];
    const float* wq   = (const float*)d_in[1];
    const float* wk   = (const float*)d_in[2];
    const float* wv   = (const float*)d_in[3];
    const float* wo   = (const float*)d_in[4];
    const float* sinb = (const float*)d_in[5];
    const float* cosb = (const float*)d_in[6];
    float* out = (float*)d_out;

    float *q, *k, *v;
    __nv_bfloat16 *xh, *xl, *yh, *yl, *kh, *kl, *vh, *vl;
    __nv_bfloat16 *wqh, *wql, *wkh, *wkl, *wvh, *wvl, *woh, *wol;
    cudaGetSymbolAddress((void**)&q, g_q);
    cudaGetSymbolAddress((void**)&k, g_k);
    cudaGetSymbolAddress((void**)&v, g_v);
    cudaGetSymbolAddress((void**)&xh, g_xh);
    cudaGetSymbolAddress((void**)&xl, g_xl);
    cudaGetSymbolAddress((void**)&yh, g_yh);
    cudaGetSymbolAddress((void**)&yl, g_yl);
    cudaGetSymbolAddress((void**)&kh, g_kh);
    cudaGetSymbolAddress((void**)&kl, g_kl);
    cudaGetSymbolAddress((void**)&vh, g_vh);
    cudaGetSymbolAddress((void**)&vl, g_vl);
    cudaGetSymbolAddress((void**)&wqh, g_wqh);
    cudaGetSymbolAddress((void**)&wql, g_wql);
    cudaGetSymbolAddress((void**)&wkh, g_wkh);
    cudaGetSymbolAddress((void**)&wkl, g_wkl);
    cudaGetSymbolAddress((void**)&wvh, g_wvh);
    cudaGetSymbolAddress((void**)&wvl, g_wvl);
    cudaGetSymbolAddress((void**)&woh, g_woh);
    cudaGetSymbolAddress((void**)&wol, g_wol);

    cudaFuncSetAttribute(attn_tc, cudaFuncAttributeMaxDynamicSharedMemorySize,
                         ATT_SMEM_BYTES);

    // ---- split x, transpose+split weights ----
    {
        int n4 = MROWS * CDIM / 4;
        split_f32<<<(n4 + 255) / 256, 256>>>(x, xh, xl, n4);
    }
    dim3 tb(32, 8);
    transpose_split<<<dim3(CDIM / 32, CDIM / 32), tb>>>(wq, wqh, wql, CDIM, CDIM);
    transpose_split<<<dim3(KVDIM / 32, CDIM / 32), tb>>>(wk, wkh, wkl, CDIM, KVDIM);
    transpose_split<<<dim3(KVDIM / 32, CDIM / 32), tb>>>(wv, wvh, wvl, CDIM, KVDIM);
    transpose_split<<<dim3(CDIM / 32, CDIM / 32), tb>>>(wo, woh, wol, CDIM, CDIM);

    // ---- QKV projections (tensor-core split-bf16) ----
    gemm_bf16split<<<dim3(CDIM / BN, MROWS / BM), 512>>>(xh, xl, wqh, wql, q,
                                                         MROWS, CDIM, CDIM);
    gemm_bf16split<<<dim3(KVDIM / BN, MROWS / BM), 512>>>(xh, xl, wkh, wkl, k,
                                                          MROWS, KVDIM, CDIM);
    gemm_bf16split<<<dim3(KVDIM / BN, MROWS / BM), 512>>>(xh, xl, wvh, wvl, v,
                                                          MROWS, KVDIM, CDIM);

    // ---- RoPE (q also gets 1/sqrt(hd)) ----
    const float scale = 0.08838834764831845f;  // 1/sqrt(128)
    int nq = MROWS * NHEAD * 64;
    int nk = MROWS * NKV * 64;
    rope_kernel<<<(nq + 255) / 256, 256>>>(q, sinb, cosb, NHEAD, CDIM, scale, nq);
    rope_kernel<<<(nk + 255) / 256, 256>>>(k, sinb, cosb, NKV, KVDIM, 1.0f, nk);

    // ---- split K (post-RoPE) and V to bf16 hi/lo ----
    {
        int n4 = MROWS * KVDIM / 4;
        split_f32<<<(n4 + 255) / 256, 256>>>(k, kh, kl, n4);
        split_f32<<<(n4 + 255) / 256, 256>>>(v, vh, vl, n4);
    }

    // ---- Tensor-core attention (writes split bf16 y directly) ----
    attn_tc<<<dim3(SEQ / 64, NHEAD, BATCH), 128, ATT_SMEM_BYTES>>>(
        q, kh, kl, vh, vl, yh, yl);

    // ---- Output projection ----
    gemm_bf16split<<<dim3(CDIM / BN, MROWS / BM), 512>>>(yh, yl, woh, wol, out,
                                                         MROWS, CDIM, CDIM);
}

// round 17
// speedup vs baseline: 1.6553x; 1.0728x over previous
#include <cuda_runtime.h>
#include <cuda_bf16.h>
#include <math.h>
#include <stdint.h>

// Problem constants
#define BATCH 8
#define SEQ   1024
#define CDIM  2048
#define NHEAD 16
#define NKV   4
#define HD    128
#define MROWS (BATCH*SEQ)          // 8192
#define KVDIM (NKV*HD)             // 512

// ---------------------------------------------------------------------------
// Scratch (__device__ globals; no allocation allowed)
// ---------------------------------------------------------------------------
__device__ __align__(16) float g_q[(size_t)MROWS * CDIM];    // 64 MB
__device__ __align__(16) float g_k[(size_t)MROWS * KVDIM];   // 16 MB
__device__ __align__(16) float g_v[(size_t)MROWS * KVDIM];   // 16 MB

// bf16 hi/lo split buffers
__device__ __align__(16) __nv_bfloat16 g_xh[(size_t)MROWS * CDIM];
__device__ __align__(16) __nv_bfloat16 g_xl[(size_t)MROWS * CDIM];
__device__ __align__(16) __nv_bfloat16 g_yh[(size_t)MROWS * CDIM];
__device__ __align__(16) __nv_bfloat16 g_yl[(size_t)MROWS * CDIM];
__device__ __align__(16) __nv_bfloat16 g_kh[(size_t)MROWS * KVDIM];
__device__ __align__(16) __nv_bfloat16 g_kl[(size_t)MROWS * KVDIM];
__device__ __align__(16) __nv_bfloat16 g_vh[(size_t)MROWS * KVDIM];
__device__ __align__(16) __nv_bfloat16 g_vl[(size_t)MROWS * KVDIM];
// transposed + split weights: [N][K] layout (k-contiguous)
__device__ __align__(16) __nv_bfloat16 g_wqh[(size_t)CDIM * CDIM];
__device__ __align__(16) __nv_bfloat16 g_wql[(size_t)CDIM * CDIM];
__device__ __align__(16) __nv_bfloat16 g_wkh[(size_t)KVDIM * CDIM];
__device__ __align__(16) __nv_bfloat16 g_wkl[(size_t)KVDIM * CDIM];
__device__ __align__(16) __nv_bfloat16 g_wvh[(size_t)KVDIM * CDIM];
__device__ __align__(16) __nv_bfloat16 g_wvl[(size_t)KVDIM * CDIM];
__device__ __align__(16) __nv_bfloat16 g_woh[(size_t)CDIM * CDIM];
__device__ __align__(16) __nv_bfloat16 g_wol[(size_t)CDIM * CDIM];

// ---------------------------------------------------------------------------
__device__ __forceinline__ void split2(float x, float y, uint32_t& hi, uint32_t& lo) {
    __nv_bfloat16 hx = __float2bfloat16(x), hy = __float2bfloat16(y);
    __nv_bfloat162 hp; hp.x = hx; hp.y = hy;
    __nv_bfloat162 lp;
    lp.x = __float2bfloat16(x - __bfloat162float(hx));
    lp.y = __float2bfloat16(y - __bfloat162float(hy));
    hi = *(uint32_t*)&hp;
    lo = *(uint32_t*)&lp;
}

// ---------------------------------------------------------------------------
// Split fp32 -> (hi, lo) bf16 pair, elementwise, same layout. n4 = n/4.
// ---------------------------------------------------------------------------
__global__ void split_f32(const float* __restrict__ in,
                          __nv_bfloat16* __restrict__ hi,
                          __nv_bfloat16* __restrict__ lo, int n4)
{
    int i = blockIdx.x * blockDim.x + threadIdx.x;
    if (i >= n4) return;
    float4 v = ((const float4*)in)[i];
    uint32_t h0, l0, h1, l1;
    split2(v.x, v.y, h0, l0);
    split2(v.z, v.w, h1, l1);
    ((uint32_t*)hi)[2 * i]     = h0;
    ((uint32_t*)hi)[2 * i + 1] = h1;
    ((uint32_t*)lo)[2 * i]     = l0;
    ((uint32_t*)lo)[2 * i + 1] = l1;
}

// ---------------------------------------------------------------------------
// Transpose + split: w [K][N] fp32  ->  th, tl [N][K] bf16.
// ---------------------------------------------------------------------------
__global__ void transpose_split(const float* __restrict__ w,
                                __nv_bfloat16* __restrict__ th,
                                __nv_bfloat16* __restrict__ tl, int K, int N)
{
    __shared__ float tile[32][33];
    int x  = blockIdx.x * 32 + threadIdx.x;
    int y0 = blockIdx.y * 32;
#pragma unroll
    for (int r = threadIdx.y; r < 32; r += 8)
        tile[r][threadIdx.x] = w[(size_t)(y0 + r) * N + x];
    __syncthreads();
    int n0 = blockIdx.x * 32;
    int kk = y0 + threadIdx.x;
#pragma unroll
    for (int r = threadIdx.y; r < 32; r += 8) {
        float v = tile[threadIdx.x][r];
        __nv_bfloat16 h = __float2bfloat16(v);
        th[(size_t)(n0 + r) * K + kk] = h;
        tl[(size_t)(n0 + r) * K + kk] = __float2bfloat16(v - __bfloat162float(h));
    }
}

// ---------------------------------------------------------------------------
// mma.sync m16n8k16 bf16 -> f32 (hardware-validated fragment layouts)
// ---------------------------------------------------------------------------
__device__ __forceinline__ void mma_bf16(float c[4], const uint32_t a[4],
                                         const uint32_t b[2]) {
    asm volatile(
        "mma.sync.aligned.m16n8k16.row.col.f32.bf16.bf16.f32 "
        "{%0,%1,%2,%3}, {%4,%5,%6,%7}, {%8,%9}, {%0,%1,%2,%3};\n"
        : "+f"(c[0]), "+f"(c[1]), "+f"(c[2]), "+f"(c[3])
        : "r"(a[0]), "r"(a[1]), "r"(a[2]), "r"(a[3]), "r"(b[0]), "r"(b[1]));
}

__device__ __forceinline__ uint32_t lds32(const __nv_bfloat16* s, int off_half) {
    return *(const uint32_t*)(s + off_half);
}

// ---------------------------------------------------------------------------
// Split-bf16 tensor-core GEMM (validated in the 2698us run). Unchanged.
//   C[M][N] fp32 = A[M][K] @ B[N][K]^T  as  Ah*Bh + Al*Bh + Ah*Bl
// ---------------------------------------------------------------------------
#define BM  128
#define BN  128
#define BKT 32
#define SPAD 40

__global__ __launch_bounds__(512, 1) void gemm_bf16split(
    const __nv_bfloat16* __restrict__ Ah, const __nv_bfloat16* __restrict__ Al,
    const __nv_bfloat16* __restrict__ Bh, const __nv_bfloat16* __restrict__ Bl,
    float* __restrict__ C, int M, int N, int K)
{
    __shared__ __nv_bfloat16 sAh[BM * SPAD];
    __shared__ __nv_bfloat16 sAl[BM * SPAD];
    __shared__ __nv_bfloat16 sBh[BN * SPAD];
    __shared__ __nv_bfloat16 sBl[BN * SPAD];

    const int tid  = threadIdx.x;
    const int warp = tid >> 5;
    const int lane = tid & 31;
    const int g = lane >> 2;
    const int t = lane & 3;
    const int wm = (warp >> 2) * 32;
    const int wn = (warp & 3) * 32;

    const int lrow = tid >> 2;
    const int lcol = (tid & 3) * 8;

    const size_t aoff = (size_t)(blockIdx.y * BM + lrow) * K + lcol;
    const size_t boff = (size_t)(blockIdx.x * BN + lrow) * K + lcol;
    const int srow = lrow * SPAD + lcol;

    float acc[2][4][4];
#pragma unroll
    for (int mi = 0; mi < 2; mi++)
#pragma unroll
        for (int nj = 0; nj < 4; nj++)
#pragma unroll
            for (int c = 0; c < 4; c++) acc[mi][nj][c] = 0.f;

    {
        uint4 a_h = *(const uint4*)(Ah + aoff);
        uint4 a_l = *(const uint4*)(Al + aoff);
        uint4 b_h = *(const uint4*)(Bh + boff);
        uint4 b_l = *(const uint4*)(Bl + boff);
        *(uint4*)(sAh + srow) = a_h;
        *(uint4*)(sAl + srow) = a_l;
        *(uint4*)(sBh + srow) = b_h;
        *(uint4*)(sBl + srow) = b_l;
    }
    __syncthreads();

    const int ktiles = K / BKT;
    for (int kt = 0; kt < ktiles; kt++) {
        uint4 pa_h, pa_l, pb_h, pb_l;
        if (kt + 1 < ktiles) {
            const int k0 = (kt + 1) * BKT;
            pa_h = *(const uint4*)(Ah + aoff + k0);
            pa_l = *(const uint4*)(Al + aoff + k0);
            pb_h = *(const uint4*)(Bh + boff + k0);
            pb_l = *(const uint4*)(Bl + boff + k0);
        }

#pragma unroll
        for (int kk = 0; kk < 2; kk++) {
            const int kbase = kk * 16 + 2 * t;
            uint32_t ah[2][4], al[2][4];
#pragma unroll
            for (int mi = 0; mi < 2; mi++) {
                const int r0 = wm + mi * 16 + g;
                ah[mi][0] = lds32(sAh, r0 * SPAD + kbase);
                ah[mi][1] = lds32(sAh, (r0 + 8) * SPAD + kbase);
                ah[mi][2] = lds32(sAh, r0 * SPAD + kbase + 8);
                ah[mi][3] = lds32(sAh, (r0 + 8) * SPAD + kbase + 8);
                al[mi][0] = lds32(sAl, r0 * SPAD + kbase);
                al[mi][1] = lds32(sAl, (r0 + 8) * SPAD + kbase);
                al[mi][2] = lds32(sAl, r0 * SPAD + kbase + 8);
                al[mi][3] = lds32(sAl, (r0 + 8) * SPAD + kbase + 8);
            }
            uint32_t bh[4][2], bl[4][2];
#pragma unroll
            for (int nj = 0; nj < 4; nj++) {
                const int rb = (wn + nj * 8 + g) * SPAD + kbase;
                bh[nj][0] = lds32(sBh, rb);
                bh[nj][1] = lds32(sBh, rb + 8);
                bl[nj][0] = lds32(sBl, rb);
                bl[nj][1] = lds32(sBl, rb + 8);
            }
#pragma unroll
            for (int mi = 0; mi < 2; mi++)
#pragma unroll
                for (int nj = 0; nj < 4; nj++) {
                    mma_bf16(acc[mi][nj], ah[mi], bh[nj]);
                    mma_bf16(acc[mi][nj], al[mi], bh[nj]);
                    mma_bf16(acc[mi][nj], ah[mi], bl[nj]);
                }
        }
        __syncthreads();
        if (kt + 1 < ktiles) {
            *(uint4*)(sAh + srow) = pa_h;
            *(uint4*)(sAl + srow) = pa_l;
            *(uint4*)(sBh + srow) = pb_h;
            *(uint4*)(sBl + srow) = pb_l;
        }
        __syncthreads();
    }

#pragma unroll
    for (int mi = 0; mi < 2; mi++) {
        const int row = blockIdx.y * BM + wm + mi * 16 + g;
#pragma unroll
        for (int nj = 0; nj < 4; nj++) {
            const int col = blockIdx.x * BN + wn + nj * 8 + 2 * t;
            float2 v01 = make_float2(acc[mi][nj][0], acc[mi][nj][1]);
            float2 v23 = make_float2(acc[mi][nj][2], acc[mi][nj][3]);
            *(float2*)(C + (size_t)row * N + col)       = v01;
            *(float2*)(C + (size_t)(row + 8) * N + col) = v23;
        }
    }
}

// ---------------------------------------------------------------------------
// RoPE (in place), scale folds 1/sqrt(hd) into q.
// ---------------------------------------------------------------------------
__global__ void rope_kernel(float* __restrict__ buf,
                            const float* __restrict__ sinb,
                            const float* __restrict__ cosb,
                            int nheads, int rowwidth, float scale, int total)
{
    int idx = blockIdx.x * blockDim.x + threadIdx.x;
    if (idx >= total) return;
    int d = idx & 63;
    int tmp = idx >> 6;
    int h = tmp % nheads;
    int row = tmp / nheads;
    int t = row & (SEQ - 1);
    float* p = buf + (size_t)row * rowwidth + h * HD;
    float a = p[d], b = p[d + 64];
    float c0 = cosb[t * HD + d],      s0 = sinb[t * HD + d];
    float c1 = cosb[t * HD + d + 64], s1 = sinb[t * HD + d + 64];
    p[d]      = (a * c0 - b * s0) * scale;
    p[d + 64] = (b * c1 + a * s1) * scale;
}

// ---------------------------------------------------------------------------
// Tensor-core flash attention (mma.sync), split-bf16 3-pass QK^T and PV.
// q-tile 128 rows, 256 threads (8 warps); per-warp work same as the
// validated 64-row version (16 rows/warp); KV tile-loads drop ~1.9x.
// Grid: (SEQ/128, NHEAD, BATCH).
// smem 71680 B; sQ staging [128][132] fp32 = 67584 B aliases K/V region.
// ---------------------------------------------------------------------------
#define KPADA 136
#define VPAD  72
#define ATT_SMEM_BYTES ((8704 * 2 + 9216 * 2) * 2)   // 71680

__global__ __launch_bounds__(256) void attn_tc(
    const float* __restrict__ q,
    const __nv_bfloat16* __restrict__ kh, const __nv_bfloat16* __restrict__ kl,
    const __nv_bfloat16* __restrict__ vh, const __nv_bfloat16* __restrict__ vl,
    __nv_bfloat16* __restrict__ yh, __nv_bfloat16* __restrict__ yl)
{
    extern __shared__ __nv_bfloat16 sm[];
    __nv_bfloat16* sKh = sm;            // 8704 halves
    __nv_bfloat16* sKl = sm + 8704;
    __nv_bfloat16* sVh = sm + 17408;    // 9216 halves
    __nv_bfloat16* sVl = sm + 26624;
    float* sQ = (float*)sm;             // [128][132] fp32, pre-loop only

    const int qt = blockIdx.x, h = blockIdx.y, b = blockIdx.z;
    const int kvh = h & (NKV - 1);
    const int tid = threadIdx.x, lane = tid & 31, warp = tid >> 5;
    const int g = lane >> 2, t = lane & 3;
    const int row0  = warp * 16 + g;        // 8 warps x 16 rows = 128
    const int trow0 = qt * 128 + row0;
    const int trow1 = trow0 + 8;

    // ---- stage Q tile (coalesced) ----
    {
        const float* qb = q + (size_t)(b * SEQ + qt * 128) * CDIM + h * HD;
        for (int i = tid; i < 128 * 32; i += 256) {
            int r = i >> 5, c = i & 31;
            *(float4*)&sQ[r * 132 + c * 4] = *(const float4*)(qb + (size_t)r * CDIM + c * 4);
        }
    }
    __syncthreads();

    // ---- extract Q A-fragments, hi/lo split ----
    uint32_t qhf[8][4], qlf[8][4];
#pragma unroll
    for (int kb = 0; kb < 8; kb++) {
        int k0 = kb * 16 + 2 * t;
        float2 f0 = *(float2*)&sQ[row0 * 132 + k0];
        float2 f1 = *(float2*)&sQ[(row0 + 8) * 132 + k0];
        float2 f2 = *(float2*)&sQ[row0 * 132 + k0 + 8];
        float2 f3 = *(float2*)&sQ[(row0 + 8) * 132 + k0 + 8];
        split2(f0.x, f0.y, qhf[kb][0], qlf[kb][0]);
        split2(f1.x, f1.y, qhf[kb][1], qlf[kb][1]);
        split2(f2.x, f2.y, qhf[kb][2], qlf[kb][2]);
        split2(f3.x, f3.y, qhf[kb][3], qlf[kb][3]);
    }
    __syncthreads();

    float O[16][4];
#pragma unroll
    for (int nb = 0; nb < 16; nb++)
#pragma unroll
        for (int c = 0; c < 4; c++) O[nb][c] = 0.f;
    float m0 = -INFINITY, m1 = -INFINITY, l0 = 0.f, l1 = 0.f;

    const int ntiles = 2 * qt + 2;          // key tiles of 64
    for (int kt = 0; kt < ntiles; kt++) {
        // ---- load K tile (straight) and V tile (transposed) ----
        {
            const size_t kvrow = (size_t)(b * SEQ + kt * 64);
            for (int i = tid; i < 1024; i += 256) {
                int key = i >> 4, seg = i & 15;
                size_t src = (kvrow + key) * KVDIM + (size_t)kvh * HD + seg * 8;
                *(uint4*)&sKh[key * KPADA + seg * 8] = *(const uint4*)(kh + src);
                *(uint4*)&sKl[key * KPADA + seg * 8] = *(const uint4*)(kl + src);
                uint4 v4h = *(const uint4*)(vh + src);
                uint4 v4l = *(const uint4*)(vl + src);
                int d0 = seg * 8;
                const __nv_bfloat16* ph = (const __nv_bfloat16*)&v4h;
                const __nv_bfloat16* pl = (const __nv_bfloat16*)&v4l;
#pragma unroll
                for (int e = 0; e < 8; e++) {
                    sVh[(d0 + e) * VPAD + key] = ph[e];
                    sVl[(d0 + e) * VPAD + key] = pl[e];
                }
            }
        }
        __syncthreads();

        // ---- scores S = q . k^T (3-pass split) ----
        float S[8][4];
#pragma unroll
        for (int nb = 0; nb < 8; nb++)
#pragma unroll
            for (int c = 0; c < 4; c++) S[nb][c] = 0.f;

#pragma unroll
        for (int kb = 0; kb < 8; kb++) {
#pragma unroll
            for (int nb = 0; nb < 8; nb++) {
                const int ba = (nb * 8 + g) * KPADA + kb * 16 + 2 * t;
                uint32_t bh[2], bl[2];
                bh[0] = lds32(sKh, ba);
                bh[1] = lds32(sKh, ba + 8);
                bl[0] = lds32(sKl, ba);
                bl[1] = lds32(sKl, ba + 8);
                mma_bf16(S[nb], qhf[kb], bh);
                mma_bf16(S[nb], qlf[kb], bh);
                mma_bf16(S[nb], qhf[kb], bl);
            }
        }

        // ---- causal mask (last two tiles may cross the diagonal) ----
        if (kt >= 2 * qt) {
#pragma unroll
            for (int nb = 0; nb < 8; nb++) {
                int kc = kt * 64 + nb * 8 + 2 * t;
                if (kc > trow0)     S[nb][0] = -INFINITY;
                if (kc + 1 > trow0) S[nb][1] = -INFINITY;
                if (kc > trow1)     S[nb][2] = -INFINITY;
                if (kc + 1 > trow1) S[nb][3] = -INFINITY;
            }
        }

        // ---- online softmax ----
        float mx0 = m0, mx1 = m1;
#pragma unroll
        for (int nb = 0; nb < 8; nb++) {
            mx0 = fmaxf(mx0, fmaxf(S[nb][0], S[nb][1]));
            mx1 = fmaxf(mx1, fmaxf(S[nb][2], S[nb][3]));
        }
        mx0 = fmaxf(mx0, __shfl_xor_sync(0xffffffffu, mx0, 1));
        mx0 = fmaxf(mx0, __shfl_xor_sync(0xffffffffu, mx0, 2));
        mx1 = fmaxf(mx1, __shfl_xor_sync(0xffffffffu, mx1, 1));
        mx1 = fmaxf(mx1, __shfl_xor_sync(0xffffffffu, mx1, 2));

        float al0 = __expf(m0 - mx0);
        float al1 = __expf(m1 - mx1);
        m0 = mx0; m1 = mx1;

        float ps0 = 0.f, ps1 = 0.f;
#pragma unroll
        for (int nb = 0; nb < 8; nb++) {
            S[nb][0] = __expf(S[nb][0] - m0);
            S[nb][1] = __expf(S[nb][1] - m0);
            S[nb][2] = __expf(S[nb][2] - m1);
            S[nb][3] = __expf(S[nb][3] - m1);
            ps0 += S[nb][0] + S[nb][1];
            ps1 += S[nb][2] + S[nb][3];
        }
        l0 = l0 * al0 + ps0;
        l1 = l1 * al1 + ps1;

#pragma unroll
        for (int nb = 0; nb < 16; nb++) {
            O[nb][0] *= al0; O[nb][1] *= al0;
            O[nb][2] *= al1; O[nb][3] *= al1;
        }

        // ---- PV: O += P @ V (3-pass split), P built from S fragments ----
#pragma unroll
        for (int kb = 0; kb < 4; kb++) {
            uint32_t aPh[4], aPl[4];
            split2(S[2 * kb][0],     S[2 * kb][1],     aPh[0], aPl[0]);
            split2(S[2 * kb][2],     S[2 * kb][3],     aPh[1], aPl[1]);
            split2(S[2 * kb + 1][0], S[2 * kb + 1][1], aPh[2], aPl[2]);
            split2(S[2 * kb + 1][2], S[2 * kb + 1][3], aPh[3], aPl[3]);
#pragma unroll
            for (int nb = 0; nb < 16; nb++) {
                const int ba = (nb * 8 + g) * VPAD + kb * 16 + 2 * t;
                uint32_t bh[2], bl[2];
                bh[0] = lds32(sVh, ba);
                bh[1] = lds32(sVh, ba + 8);
                bl[0] = lds32(sVl, ba);
                bl[1] = lds32(sVl, ba + 8);
                mma_bf16(O[nb], aPh, bh);
                mma_bf16(O[nb], aPl, bh);
                mma_bf16(O[nb], aPh, bl);
            }
        }
        __syncthreads();   // tiles consumed; safe to overwrite next iter
    }

    // ---- final normalize + split-bf16 store ----
    l0 += __shfl_xor_sync(0xffffffffu, l0, 1);
    l0 += __shfl_xor_sync(0xffffffffu, l0, 2);
    l1 += __shfl_xor_sync(0xffffffffu, l1, 1);
    l1 += __shfl_xor_sync(0xffffffffu, l1, 2);
    const float inv0 = 1.f / l0, inv1 = 1.f / l1;

    const size_t ybase0 = (size_t)(b * SEQ + trow0) * CDIM + h * HD;
    const size_t ybase1 = (size_t)(b * SEQ + trow1) * CDIM + h * HD;
#pragma unroll
    for (int nb = 0; nb < 16; nb++) {
        const int d = nb * 8 + 2 * t;
        uint32_t hi, lo;
        split2(O[nb][0] * inv0, O[nb][1] * inv0, hi, lo);
        *(uint32_t*)&yh[ybase0 + d] = hi;
        *(uint32_t*)&yl[ybase0 + d] = lo;
        split2(O[nb][2] * inv1, O[nb][3] * inv1, hi, lo);
        *(uint32_t*)&yh[ybase1 + d] = hi;
        *(uint32_t*)&yl[ybase1 + d] = lo;
    }
}

// ---------------------------------------------------------------------------
extern "C" void kernel_launch(void* const* d_in, const int* in_sizes, int n_in,
                              void* d_out, int out_size)
{
    const float* x    = (const float*)d_in[0];
    const float* wq   = (const float*)d_in[1];
    const float* wk   = (const float*)d_in[2];
    const float* wv   = (const float*)d_in[3];
    const float* wo   = (const float*)d_in[4];
    const float* sinb = (const float*)d_in[5];
    const float* cosb = (const float*)d_in[6];
    float* out = (float*)d_out;

    float *q, *k, *v;
    __nv_bfloat16 *xh, *xl, *yh, *yl, *kh, *kl, *vh, *vl;
    __nv_bfloat16 *wqh, *wql, *wkh, *wkl, *wvh, *wvl, *woh, *wol;
    cudaGetSymbolAddress((void**)&q, g_q);
    cudaGetSymbolAddress((void**)&k, g_k);
    cudaGetSymbolAddress((void**)&v, g_v);
    cudaGetSymbolAddress((void**)&xh, g_xh);
    cudaGetSymbolAddress((void**)&xl, g_xl);
    cudaGetSymbolAddress((void**)&yh, g_yh);
    cudaGetSymbolAddress((void**)&yl, g_yl);
    cudaGetSymbolAddress((void**)&kh, g_kh);
    cudaGetSymbolAddress((void**)&kl, g_kl);
    cudaGetSymbolAddress((void**)&vh, g_vh);
    cudaGetSymbolAddress((void**)&vl, g_vl);
    cudaGetSymbolAddress((void**)&wqh, g_wqh);
    cudaGetSymbolAddress((void**)&wql, g_wql);
    cudaGetSymbolAddress((void**)&wkh, g_wkh);
    cudaGetSymbolAddress((void**)&wkl, g_wkl);
    cudaGetSymbolAddress((void**)&wvh, g_wvh);
    cudaGetSymbolAddress((void**)&wvl, g_wvl);
    cudaGetSymbolAddress((void**)&woh, g_woh);
    cudaGetSymbolAddress((void**)&wol, g_wol);

    cudaFuncSetAttribute(attn_tc, cudaFuncAttributeMaxDynamicSharedMemorySize,
                         ATT_SMEM_BYTES);

    // ---- split x, transpose+split weights ----
    {
        int n4 = MROWS * CDIM / 4;
        split_f32<<<(n4 + 255) / 256, 256>>>(x, xh, xl, n4);
    }
    dim3 tb(32, 8);
    transpose_split<<<dim3(CDIM / 32, CDIM / 32), tb>>>(wq, wqh, wql, CDIM, CDIM);
    transpose_split<<<dim3(KVDIM / 32, CDIM / 32), tb>>>(wk, wkh, wkl, CDIM, KVDIM);
    transpose_split<<<dim3(KVDIM / 32, CDIM / 32), tb>>>(wv, wvh, wvl, CDIM, KVDIM);
    transpose_split<<<dim3(CDIM / 32, CDIM / 32), tb>>>(wo, woh, wol, CDIM, CDIM);

    // ---- QKV projections (mma.sync split-bf16, validated) ----
    gemm_bf16split<<<dim3(CDIM / BN, MROWS / BM), 512>>>(xh, xl, wqh, wql, q,
                                                         MROWS, CDIM, CDIM);
    gemm_bf16split<<<dim3(KVDIM / BN, MROWS / BM), 512>>>(xh, xl, wkh, wkl, k,
                                                          MROWS, KVDIM, CDIM);
    gemm_bf16split<<<dim3(KVDIM / BN, MROWS / BM), 512>>>(xh, xl, wvh, wvl, v,
                                                          MROWS, KVDIM, CDIM);

    // ---- RoPE (q also gets 1/sqrt(hd)) ----
    const float scale = 0.08838834764831845f;  // 1/sqrt(128)
    int nq = MROWS * NHEAD * 64;
    int nk = MROWS * NKV * 64;
    rope_kernel<<<(nq + 255) / 256, 256>>>(q, sinb, cosb, NHEAD, CDIM, scale, nq);
    rope_kernel<<<(nk + 255) / 256, 256>>>(k, sinb, cosb, NKV, KVDIM, 1.0f, nk);

    // ---- split K (post-RoPE) and V to bf16 hi/lo ----
    {
        int n4 = MROWS * KVDIM / 4;
        split_f32<<<(n4 + 255) / 256, 256>>>(k, kh, kl, n4);
        split_f32<<<(n4 + 255) / 256, 256>>>(v, vh, vl, n4);
    }

    // ---- Tensor-core attention (128-row q tiles, writes split bf16 y) ----
    attn_tc<<<dim3(SEQ / 128, NHEAD, BATCH), 256, ATT_SMEM_BYTES>>>(
        q, kh, kl, vh, vl, yh, yl);

    // ---- Output projection ----
    gemm_bf16split<<<dim3(CDIM / BN, MROWS / BM), 512>>>(yh, yl, woh, wol, out,
                                                         MROWS, CDIM, CDIM);
}